// round 1
// baseline (speedup 1.0000x reference)
#include <cuda_runtime.h>
#include <cstdint>

// Problem constants
#define BATCH 8
#define CH    96
#define NPIX  3136          // 56*56
#define NODES (BATCH*NPIX)  // 25088
#define KNN   9
#define COUT  192

// ---------------- device scratch (static globals; no allocation) ----------------
__device__ float g_xf[NODES*CH];        // [node, c] node features
__device__ float g_sq[NODES];           // per-node squared norm
__device__ int   g_nn[NODES*KNN];       // global neighbor indices, topk order
__device__ int   g_ki[NODES];           // kept degree per node
__device__ float g_W1c[CH*64];          // folded kmap@kfc
__device__ float g_b1c[64];
__device__ float g_W2c[64*KNN];         // folded kmu@kdec
__device__ float g_b2c[KNN];
__device__ float g_Wcat1[192*96];       // [Wa-Wb ; Wb] of ec1
__device__ float g_Wcat2[192*96];       // of ec2
__device__ float g_Wcat3[192*192];      // [io_w@Up1 ; fc_w@Up2]
__device__ float g_bias3[192];
__device__ float g_A1[NODES*192];       // concat feature buffer 1
__device__ float g_A2[NODES*192];       // concat feature buffer 2
__device__ float g_h1[NODES*CH];        // conv1 output

// ---------------- transpose x[B,C,H,W] -> xf[node, c] ----------------
__global__ void transpose_kernel(const float* __restrict__ x) {
    __shared__ float t[32][33];
    int b = blockIdx.z, c0 = blockIdx.y * 32, n0 = blockIdx.x * 32;
    int tx = threadIdx.x, ty = threadIdx.y;
    // read x[b][c0+ty][n0+tx], coalesced along n
    t[ty][tx] = x[((size_t)b*CH + (c0+ty))*NPIX + (n0+tx)];
    __syncthreads();
    // write xf[(b*N + n0+ty)][c0+tx], coalesced along c
    g_xf[((size_t)b*NPIX + (n0+ty))*CH + (c0+tx)] = t[tx][ty];
}

// ---------------- per-node squared norm ----------------
__global__ void sq_kernel() {
    int i = blockIdx.x * blockDim.x + threadIdx.x;
    if (i >= NODES) return;
    const float4* p = (const float4*)(g_xf + (size_t)i*CH);
    float a0=0,a1=0,a2=0,a3=0;
#pragma unroll
    for (int c4 = 0; c4 < CH/4; ++c4) {
        float4 v = p[c4];
        a0 = fmaf(v.x, v.x, a0);
        a1 = fmaf(v.y, v.y, a1);
        a2 = fmaf(v.z, v.z, a2);
        a3 = fmaf(v.w, v.w, a3);
    }
    g_sq[i] = (a0+a1)+(a2+a3);
}

// ---------------- weight folding kernels ----------------
__global__ void prep_k1(const float* __restrict__ kmap_w, const float* __restrict__ kmap_b,
                        const float* __restrict__ kfc_w,  const float* __restrict__ kfc_b) {
    int idx = blockIdx.x * blockDim.x + threadIdx.x;
    if (idx < CH*64) {
        int c = idx / 64, h = idx % 64;
        float acc = 0.f;
        for (int k = 0; k < 500; ++k) acc = fmaf(kmap_w[c*500+k], kfc_w[k*64+h], acc);
        g_W1c[idx] = acc;
    }
    if (idx < 64) {
        float acc = kfc_b[idx];
        for (int k = 0; k < 500; ++k) acc = fmaf(kmap_b[k], kfc_w[k*64+idx], acc);
        g_b1c[idx] = acc;
    }
}

__global__ void prep_k2(const float* __restrict__ kmu_w, const float* __restrict__ kmu_b,
                        const float* __restrict__ kdec_w, const float* __restrict__ kdec_b) {
    int idx = blockIdx.x * blockDim.x + threadIdx.x;
    if (idx < 64*KNN) {
        int h = idx / KNN, j = idx % KNN;
        float acc = 0.f;
        for (int t = 0; t < 32; ++t) acc = fmaf(kmu_w[h*32+t], kdec_w[t*KNN+j], acc);
        g_W2c[idx] = acc;
    }
    if (idx < KNN) {
        float acc = kdec_b[idx];
        for (int t = 0; t < 32; ++t) acc = fmaf(kmu_b[t], kdec_w[t*KNN+idx], acc);
        g_b2c[idx] = acc;
    }
}

// ec_w is [2C, C]; rows 0..C-1 = Wa (xi part), rows C..2C-1 = Wb (xj-xi part)
// Wcat rows 0..C-1 = Wa - Wb, rows C..2C-1 = Wb
__global__ void prep_wcat(const float* __restrict__ ec_w, int which) {
    int idx = blockIdx.x * blockDim.x + threadIdx.x;
    if (idx >= 192*96) return;
    int k = idx / 96;
    float v;
    if (k < 96) v = ec_w[idx] - ec_w[idx + 96*96];
    else        v = ec_w[idx];
    if (which == 0) g_Wcat1[idx] = v; else g_Wcat2[idx] = v;
}

// Wcat3 rows 0..95 = io_w @ up_w[0:192], rows 96..191 = fc_w @ up_w[192:384]
// bias3 = io_b @ Up1 + fc_b @ Up2 + up_b
__global__ void prep_final(const float* __restrict__ io_w, const float* __restrict__ io_b,
                           const float* __restrict__ fc_w, const float* __restrict__ fc_b,
                           const float* __restrict__ up_w, const float* __restrict__ up_b) {
    int idx = blockIdx.x * blockDim.x + threadIdx.x;
    if (idx < 192*192) {
        int r = idx / 192, j = idx % 192;
        float acc = 0.f;
        if (r < 96) {
            for (int t = 0; t < 192; ++t) acc = fmaf(io_w[r*192+t], up_w[t*192+j], acc);
        } else {
            int c = r - 96;
            for (int t = 0; t < 192; ++t) acc = fmaf(fc_w[c*192+t], up_w[(192+t)*192+j], acc);
        }
        g_Wcat3[idx] = acc;
    }
    if (idx < 192) {
        float acc = up_b[idx];
        for (int t = 0; t < 192; ++t) acc = fmaf(io_b[t], up_w[t*192+idx], acc);
        for (int t = 0; t < 192; ++t) acc = fmaf(fc_b[t], up_w[(192+t)*192+idx], acc);
        g_bias3[idx] = acc;
    }
}

// ---------------- fused distance + top-9 (jax.lax.top_k semantics) ----------------
// dist(n,m) = sq[n] - 2*dot + sq[m]; keep 9 smallest, ties -> lower index first.
// Processing m ascending with strict '<' comparisons reproduces exactly that order.
__global__ __launch_bounds__(64) void dist_topk_kernel() {
    __shared__ float sfeat[32*CH];
    __shared__ float ssq[32];
    int b = blockIdx.y;
    int row = blockIdx.x * 64 + threadIdx.x;
    int g = b * NPIX + row;
    const float* xb = g_xf + (size_t)b * NPIX * CH;

    float rf[CH];
#pragma unroll
    for (int c4 = 0; c4 < CH/4; ++c4) {
        float4 v = *(const float4*)(g_xf + (size_t)g*CH + c4*4);
        rf[c4*4+0]=v.x; rf[c4*4+1]=v.y; rf[c4*4+2]=v.z; rf[c4*4+3]=v.w;
    }
    float rsq = g_sq[g];

    float d[KNN]; int id[KNN];
#pragma unroll
    for (int j = 0; j < KNN; ++j) { d[j] = 3.4e38f; id[j] = 0x7fffffff; }

    for (int m0 = 0; m0 < NPIX; m0 += 32) {
        __syncthreads();
        {   // stage 32 cols x 96 feats = 768 float4, 64 threads * 12
            const float4* src = (const float4*)(xb + (size_t)m0*CH);
            float4* dst = (float4*)sfeat;
#pragma unroll
            for (int l = 0; l < 12; ++l) dst[threadIdx.x + l*64] = src[threadIdx.x + l*64];
            if (threadIdx.x < 32) ssq[threadIdx.x] = g_sq[b*NPIX + m0 + threadIdx.x];
        }
        __syncthreads();
        for (int mm = 0; mm < 32; ++mm) {
            const float4* f = (const float4*)(sfeat + mm*CH);
            float a0=0,a1=0,a2=0,a3=0;
#pragma unroll
            for (int c4 = 0; c4 < CH/4; ++c4) {
                float4 w = f[c4];
                a0 = fmaf(rf[c4*4+0], w.x, a0);
                a1 = fmaf(rf[c4*4+1], w.y, a1);
                a2 = fmaf(rf[c4*4+2], w.z, a2);
                a3 = fmaf(rf[c4*4+3], w.w, a3);
            }
            float dot = (a0+a1)+(a2+a3);
            float dc = rsq + ssq[mm] - 2.f*dot;
            if (dc < d[KNN-1]) {
                d[KNN-1] = dc; id[KNN-1] = b*NPIX + m0 + mm;
#pragma unroll
                for (int j = KNN-1; j > 0; --j) {
                    if (d[j] < d[j-1]) {
                        float td = d[j]; d[j] = d[j-1]; d[j-1] = td;
                        int ti = id[j]; id[j] = id[j-1]; id[j-1] = ti;
                    }
                }
            }
        }
    }
#pragma unroll
    for (int j = 0; j < KNN; ++j) g_nn[(size_t)g*KNN + j] = id[j];
}

// ---------------- folded K-predictor MLP + argmax ----------------
__global__ __launch_bounds__(128) void kmlp_kernel() {
    __shared__ float sW1[CH*64];
    __shared__ float sW2[64*KNN];
    __shared__ float sb1[64];
    __shared__ float sb2[KNN];
    for (int t = threadIdx.x; t < CH*64; t += 128) sW1[t] = g_W1c[t];
    for (int t = threadIdx.x; t < 64*KNN; t += 128) sW2[t] = g_W2c[t];
    if (threadIdx.x < 64) sb1[threadIdx.x] = g_b1c[threadIdx.x];
    if (threadIdx.x < KNN) sb2[threadIdx.x] = g_b2c[threadIdx.x];
    __syncthreads();

    int i = blockIdx.x * 128 + threadIdx.x;
    float xr[CH];
#pragma unroll
    for (int c4 = 0; c4 < CH/4; ++c4) {
        float4 v = *(const float4*)(g_xf + (size_t)i*CH + c4*4);
        xr[c4*4+0]=v.x; xr[c4*4+1]=v.y; xr[c4*4+2]=v.z; xr[c4*4+3]=v.w;
    }
    float lg[KNN];
#pragma unroll
    for (int j = 0; j < KNN; ++j) lg[j] = sb2[j];

    for (int h = 0; h < 64; ++h) {
        float a0=0,a1=0,a2=0,a3=0;
#pragma unroll
        for (int c = 0; c < CH; c += 4) {
            a0 = fmaf(xr[c+0], sW1[(c+0)*64+h], a0);
            a1 = fmaf(xr[c+1], sW1[(c+1)*64+h], a1);
            a2 = fmaf(xr[c+2], sW1[(c+2)*64+h], a2);
            a3 = fmaf(xr[c+3], sW1[(c+3)*64+h], a3);
        }
        float hv = fmaxf((a0+a1)+(a2+a3) + sb1[h], 0.f);
#pragma unroll
        for (int j = 0; j < KNN; ++j) lg[j] = fmaf(hv, sW2[h*KNN+j], lg[j]);
    }
    float best = lg[0]; int bi = 0;
#pragma unroll
    for (int j = 1; j < KNN; ++j) if (lg[j] > best) { best = lg[j]; bi = j; }
    g_ki[i] = bi;
}

// ---------------- gather: A = [ki*feat_i | sum_{k<ki} feat_{nn[k]}] ----------------
__global__ void gather_kernel(int mode) {
    const float* feat = mode ? g_h1 : g_xf;
    float*       A    = mode ? g_A2 : g_A1;
    int idx = blockIdx.x * blockDim.x + threadIdx.x;
    if (idx >= NODES*CH) return;
    int i = idx / CH, c = idx % CH;
    int k = g_ki[i];
    const int* nrow = g_nn + (size_t)i*KNN;
    float s = 0.f;
    for (int e = 0; e < k; ++e) s += feat[(size_t)nrow[e]*CH + c];
    A[(size_t)i*192 + c]      = (float)k * feat[(size_t)i*CH + c];
    A[(size_t)i*192 + 96 + c] = s;
}

// ---------------- copy xf into A1[:,0:96] for the final concat ----------------
__global__ void copyxf_kernel() {
    int idx = blockIdx.x * blockDim.x + threadIdx.x;
    if (idx >= NODES*(CH/4)) return;
    int i = idx / (CH/4), c4 = idx % (CH/4);
    ((float4*)(g_A1 + (size_t)i*192))[c4] = ((const float4*)g_xf)[idx];
}

// ---------------- GEMM [25088,192] @ [192, ldw-slice of 96] ----------------
// mode 0: h1 = relu(A1@Wcat1 + ki*bias)            C=g_h1, ldc=96
// mode 1: h2 = A2@Wcat2 + ki*bias -> A1[:,96:192]  ldc=192
// mode 2: out = relu(A1@Wcat3 + bias3), transposed store into [B,192,N]
__global__ __launch_bounds__(256) void gemm_kernel(int mode, const float* __restrict__ bias_in,
                                                   float* __restrict__ dout) {
    const float* A; const float* W; const float* bias; float* C;
    int ldw, ldc, relu, usek, trans;
    if (mode == 0) { A=g_A1; W=g_Wcat1; bias=bias_in; C=g_h1;    ldw=96;  ldc=96;  relu=1; usek=1; trans=0; }
    else if (mode == 1) { A=g_A2; W=g_Wcat2; bias=bias_in; C=g_A1+96; ldw=96;  ldc=192; relu=0; usek=1; trans=0; }
    else { A=g_A1; W=g_Wcat3; bias=g_bias3; C=dout; ldw=192; ldc=192; relu=1; usek=0; trans=1; }

    __shared__ float As[16][128];
    __shared__ float Bs[16][96];
    int tid = threadIdx.x;
    int tx = tid % 16, ty = tid / 16;
    int row0 = blockIdx.x * 128;
    int col0 = blockIdx.y * 96;

    float acc[8][6];
#pragma unroll
    for (int i = 0; i < 8; ++i)
#pragma unroll
        for (int j = 0; j < 6; ++j) acc[i][j] = 0.f;

    for (int kk = 0; kk < 192; kk += 16) {
        // A tile: 128 rows x 16 k -> 512 float4
#pragma unroll
        for (int l = 0; l < 2; ++l) {
            int idx = tid + l*256;
            int r = idx >> 2, k4 = idx & 3;
            float4 v = *(const float4*)(A + (size_t)(row0 + r)*192 + kk + k4*4);
            As[k4*4+0][r] = v.x; As[k4*4+1][r] = v.y; As[k4*4+2][r] = v.z; As[k4*4+3][r] = v.w;
        }
        // B tile: 16 k x 96 cols -> 384 float4
#pragma unroll
        for (int l = 0; l < 2; ++l) {
            int idx = tid + l*256;
            if (idx < 384) {
                int k = idx / 24, c4 = idx % 24;
                float4 v = *(const float4*)(W + (size_t)(kk+k)*ldw + col0 + c4*4);
                *(float4*)&Bs[k][c4*4] = v;
            }
        }
        __syncthreads();
#pragma unroll
        for (int k = 0; k < 16; ++k) {
            float a[8], bv[6];
            float4 av0 = *(const float4*)&As[k][ty*8];
            float4 av1 = *(const float4*)&As[k][ty*8+4];
            a[0]=av0.x; a[1]=av0.y; a[2]=av0.z; a[3]=av0.w;
            a[4]=av1.x; a[5]=av1.y; a[6]=av1.z; a[7]=av1.w;
            float2 bv0 = *(const float2*)&Bs[k][tx*6];
            float2 bv1 = *(const float2*)&Bs[k][tx*6+2];
            float2 bv2 = *(const float2*)&Bs[k][tx*6+4];
            bv[0]=bv0.x; bv[1]=bv0.y; bv[2]=bv1.x; bv[3]=bv1.y; bv[4]=bv2.x; bv[5]=bv2.y;
#pragma unroll
            for (int i = 0; i < 8; ++i)
#pragma unroll
                for (int j = 0; j < 6; ++j) acc[i][j] = fmaf(a[i], bv[j], acc[i][j]);
        }
        __syncthreads();
    }

#pragma unroll
    for (int i = 0; i < 8; ++i) {
        int row = row0 + ty*8 + i;
        float kscale = usek ? (float)g_ki[row] : 1.f;
#pragma unroll
        for (int j = 0; j < 6; ++j) {
            int col = col0 + tx*6 + j;
            float v = acc[i][j] + bias[col] * kscale;
            if (relu) v = fmaxf(v, 0.f);
            if (trans) {
                int b = row / NPIX, n = row % NPIX;
                C[((size_t)(b*192 + col))*NPIX + n] = v;
            } else {
                C[(size_t)row*ldc + col] = v;
            }
        }
    }
}

// ---------------- launch ----------------
extern "C" void kernel_launch(void* const* d_in, const int* in_sizes, int n_in,
                              void* d_out, int out_size) {
    const float* x      = (const float*)d_in[0];
    const float* kmap_w = (const float*)d_in[1];
    const float* kmap_b = (const float*)d_in[2];
    const float* kfc_w  = (const float*)d_in[3];
    const float* kfc_b  = (const float*)d_in[4];
    const float* kmu_w  = (const float*)d_in[5];
    const float* kmu_b  = (const float*)d_in[6];
    const float* kdec_w = (const float*)d_in[7];
    const float* kdec_b = (const float*)d_in[8];
    const float* ec1_w  = (const float*)d_in[9];
    const float* ec1_b  = (const float*)d_in[10];
    const float* ec2_w  = (const float*)d_in[11];
    const float* ec2_b  = (const float*)d_in[12];
    const float* fc_w   = (const float*)d_in[13];
    const float* fc_b   = (const float*)d_in[14];
    const float* io_w   = (const float*)d_in[15];
    const float* io_b   = (const float*)d_in[16];
    const float* up_w   = (const float*)d_in[17];
    const float* up_b   = (const float*)d_in[18];
    float* out = (float*)d_out;

    transpose_kernel<<<dim3(NPIX/32, CH/32, BATCH), dim3(32,32)>>>(x);
    sq_kernel<<<(NODES+255)/256, 256>>>();
    prep_k1<<<(CH*64+255)/256, 256>>>(kmap_w, kmap_b, kfc_w, kfc_b);
    prep_k2<<<3, 256>>>(kmu_w, kmu_b, kdec_w, kdec_b);
    prep_wcat<<<(192*96+255)/256, 256>>>(ec1_w, 0);
    prep_wcat<<<(192*96+255)/256, 256>>>(ec2_w, 1);
    prep_final<<<(192*192+255)/256, 256>>>(io_w, io_b, fc_w, fc_b, up_w, up_b);

    dist_topk_kernel<<<dim3(NPIX/64, BATCH), 64>>>();
    kmlp_kernel<<<NODES/128, 128>>>();

    gather_kernel<<<(NODES*CH+255)/256, 256>>>(0);
    gemm_kernel<<<dim3(NODES/128, 1), 256>>>(0, ec1_b, nullptr);
    gather_kernel<<<(NODES*CH+255)/256, 256>>>(1);
    copyxf_kernel<<<(NODES*(CH/4)+255)/256, 256>>>();
    gemm_kernel<<<dim3(NODES/128, 1), 256>>>(1, ec2_b, nullptr);
    gemm_kernel<<<dim3(NODES/128, 2), 256>>>(2, nullptr, out);
    (void)in_sizes; (void)n_in; (void)out_size;
}

// round 2
// speedup vs baseline: 1.2687x; 1.2687x over previous
#include <cuda_runtime.h>
#include <cstdint>

// Problem constants
#define BATCH 8
#define CH    96
#define NPIX  3136          // 56*56
#define NODES (BATCH*NPIX)  // 25088
#define KNN   9
#define COUT  192
#define HCOL  1568          // column half for dist split

typedef unsigned long long u64;

__device__ __forceinline__ void ffma2(u64& d, u64 a, u64 b) {
    asm("fma.rn.f32x2 %0, %1, %2, %3;" : "=l"(d) : "l"(a), "l"(b), "l"(d));
}
__device__ __forceinline__ float2 unpack2(u64 a) {
    float2 r; asm("mov.b64 {%0,%1}, %2;" : "=f"(r.x), "=f"(r.y) : "l"(a)); return r;
}
__device__ __forceinline__ u64 pack2(float lo, float hi) {
    u64 r; asm("mov.b64 %0, {%1,%2};" : "=l"(r) : "f"(lo), "f"(hi)); return r;
}

// ---------------- device scratch (static globals; no allocation) ----------------
__device__ float g_xf[NODES*CH];        // [node, c] node features
__device__ float g_sq[NODES];           // per-node squared norm
__device__ int   g_nn[NODES*KNN];       // global neighbor indices, topk order
__device__ int   g_ki[NODES];           // kept degree per node
__device__ float g_pd[NODES*2*KNN];     // partial topk distances (2 halves)
__device__ int   g_pi[NODES*2*KNN];     // partial topk indices
__device__ float g_W1c[CH*64];          // folded kmap@kfc
__device__ float g_b1c[64];
__device__ float g_W2c[64*KNN];         // folded kmu@kdec
__device__ float g_b2c[KNN];
__device__ float g_Wcat1[192*96];       // [Wa-Wb ; Wb] of ec1
__device__ float g_Wcat2[192*96];       // of ec2
__device__ float g_Wcat3[192*192];      // [io_w@Up1 ; fc_w@Up2]
__device__ float g_bias3[192];
__device__ float g_A1[NODES*192];       // concat feature buffer 1
__device__ float g_A2[NODES*192];       // concat feature buffer 2
__device__ float g_h1[NODES*CH];        // conv1 output

// ---------------- transpose x[B,C,H,W] -> xf[node, c] ----------------
__global__ void transpose_kernel(const float* __restrict__ x) {
    __shared__ float t[32][33];
    int b = blockIdx.z, c0 = blockIdx.y * 32, n0 = blockIdx.x * 32;
    int tx = threadIdx.x, ty = threadIdx.y;
    t[ty][tx] = x[((size_t)b*CH + (c0+ty))*NPIX + (n0+tx)];
    __syncthreads();
    g_xf[((size_t)b*NPIX + (n0+ty))*CH + (c0+tx)] = t[tx][ty];
}

// ---------------- per-node squared norm ----------------
__global__ void sq_kernel() {
    int i = blockIdx.x * blockDim.x + threadIdx.x;
    if (i >= NODES) return;
    const float4* p = (const float4*)(g_xf + (size_t)i*CH);
    float a0=0,a1=0,a2=0,a3=0;
#pragma unroll
    for (int c4 = 0; c4 < CH/4; ++c4) {
        float4 v = p[c4];
        a0 = fmaf(v.x, v.x, a0);
        a1 = fmaf(v.y, v.y, a1);
        a2 = fmaf(v.z, v.z, a2);
        a3 = fmaf(v.w, v.w, a3);
    }
    g_sq[i] = (a0+a1)+(a2+a3);
}

// ---------------- fused weight folding (one launch) ----------------
// block ranges: [0,24) k1 | [24,27) k2 | [27,99) wcat1 | [99,171) wcat2 | [171,315) final
__global__ __launch_bounds__(256) void mega_prep(
    const float* __restrict__ kmap_w, const float* __restrict__ kmap_b,
    const float* __restrict__ kfc_w,  const float* __restrict__ kfc_b,
    const float* __restrict__ kmu_w,  const float* __restrict__ kmu_b,
    const float* __restrict__ kdec_w, const float* __restrict__ kdec_b,
    const float* __restrict__ ec1_w,  const float* __restrict__ ec2_w,
    const float* __restrict__ io_w,   const float* __restrict__ io_b,
    const float* __restrict__ fc_w,   const float* __restrict__ fc_b,
    const float* __restrict__ up_w,   const float* __restrict__ up_b)
{
    int bid = blockIdx.x;
    if (bid < 24) {
        int idx = bid*256 + threadIdx.x;
        if (idx < CH*64) {
            int c = idx / 64, h = idx % 64;
            float acc = 0.f;
            for (int k = 0; k < 500; ++k) acc = fmaf(kmap_w[c*500+k], kfc_w[k*64+h], acc);
            g_W1c[idx] = acc;
        }
        if (idx < 64) {
            float acc = kfc_b[idx];
            for (int k = 0; k < 500; ++k) acc = fmaf(kmap_b[k], kfc_w[k*64+idx], acc);
            g_b1c[idx] = acc;
        }
    } else if (bid < 27) {
        int idx = (bid-24)*256 + threadIdx.x;
        if (idx < 64*KNN) {
            int h = idx / KNN, j = idx % KNN;
            float acc = 0.f;
            for (int t = 0; t < 32; ++t) acc = fmaf(kmu_w[h*32+t], kdec_w[t*KNN+j], acc);
            g_W2c[idx] = acc;
        }
        if (idx < KNN) {
            float acc = kdec_b[idx];
            for (int t = 0; t < 32; ++t) acc = fmaf(kmu_b[t], kdec_w[t*KNN+idx], acc);
            g_b2c[idx] = acc;
        }
    } else if (bid < 99) {
        int idx = (bid-27)*256 + threadIdx.x;
        if (idx < 192*96) {
            int k = idx / 96;
            g_Wcat1[idx] = (k < 96) ? (ec1_w[idx] - ec1_w[idx + 96*96]) : ec1_w[idx];
        }
    } else if (bid < 171) {
        int idx = (bid-99)*256 + threadIdx.x;
        if (idx < 192*96) {
            int k = idx / 96;
            g_Wcat2[idx] = (k < 96) ? (ec2_w[idx] - ec2_w[idx + 96*96]) : ec2_w[idx];
        }
    } else {
        int idx = (bid-171)*256 + threadIdx.x;
        if (idx < 192*192) {
            int r = idx / 192, j = idx % 192;
            float acc = 0.f;
            if (r < 96) {
                for (int t = 0; t < 192; ++t) acc = fmaf(io_w[r*192+t], up_w[t*192+j], acc);
            } else {
                int c = r - 96;
                for (int t = 0; t < 192; ++t) acc = fmaf(fc_w[c*192+t], up_w[(192+t)*192+j], acc);
            }
            g_Wcat3[idx] = acc;
        }
        if (idx < 192) {
            float acc = up_b[idx];
            for (int t = 0; t < 192; ++t) acc = fmaf(io_b[t], up_w[t*192+idx], acc);
            for (int t = 0; t < 192; ++t) acc = fmaf(fc_b[t], up_w[(192+t)*192+idx], acc);
            g_bias3[idx] = acc;
        }
    }
}

// ---------------- fused distance + top-9, split into 2 column halves ----------------
// dist(n,m) = sq[n] - 2*dot + sq[m]; ties -> lower index (strict '<', ascending m).
// Inner dot uses packed fma.rn.f32x2 (both operands are natural adjacent pairs).
__global__ __launch_bounds__(64) void dist_topk_kernel() {
    __shared__ float sfeat[32*CH];
    __shared__ float ssq[32];
    int b    = blockIdx.z;
    int half = blockIdx.y;
    int row  = blockIdx.x * 64 + threadIdx.x;
    int g    = b * NPIX + row;
    const float* xb = g_xf + (size_t)b * NPIX * CH;

    u64 rf2[CH/2];
#pragma unroll
    for (int c2 = 0; c2 < CH/2; ++c2)
        rf2[c2] = ((const u64*)(g_xf + (size_t)g*CH))[c2];
    float rsq = g_sq[g];

    float d[KNN]; int id[KNN];
#pragma unroll
    for (int j = 0; j < KNN; ++j) { d[j] = 3.4e38f; id[j] = 0x7fffffff; }

    const int c0base = half * HCOL;
    for (int m0 = 0; m0 < HCOL; m0 += 32) {
        __syncthreads();
        {   // stage 32 cols x 96 feats = 768 float4, 64 threads x 12
            const float4* src = (const float4*)(xb + (size_t)(c0base + m0)*CH);
            float4* dst = (float4*)sfeat;
#pragma unroll
            for (int l = 0; l < 12; ++l) dst[threadIdx.x + l*64] = src[threadIdx.x + l*64];
            if (threadIdx.x < 32) ssq[threadIdx.x] = g_sq[b*NPIX + c0base + m0 + threadIdx.x];
        }
        __syncthreads();
        for (int mm = 0; mm < 32; ++mm) {
            const u64* f = (const u64*)(sfeat + mm*CH);
            u64 acc[4] = {0ull, 0ull, 0ull, 0ull};
#pragma unroll
            for (int c2 = 0; c2 < CH/2; ++c2) ffma2(acc[c2 & 3], rf2[c2], f[c2]);
            float2 s0 = unpack2(acc[0]), s1 = unpack2(acc[1]);
            float2 s2 = unpack2(acc[2]), s3 = unpack2(acc[3]);
            float dot = ((s0.x+s0.y)+(s1.x+s1.y)) + ((s2.x+s2.y)+(s3.x+s3.y));
            float dc = rsq + ssq[mm] - 2.f*dot;
            if (dc < d[KNN-1]) {
                d[KNN-1] = dc; id[KNN-1] = b*NPIX + c0base + m0 + mm;
#pragma unroll
                for (int j = KNN-1; j > 0; --j) {
                    if (d[j] < d[j-1]) {
                        float td = d[j]; d[j] = d[j-1]; d[j-1] = td;
                        int ti = id[j]; id[j] = id[j-1]; id[j-1] = ti;
                    }
                }
            }
        }
    }
#pragma unroll
    for (int j = 0; j < KNN; ++j) {
        g_pd[((size_t)g*2 + half)*KNN + j] = d[j];
        g_pi[((size_t)g*2 + half)*KNN + j] = id[j];
    }
}

// ---------------- merge two sorted 9-lists per row, (d, idx) lexicographic ----------------
__global__ void merge_topk() {
    int g = blockIdx.x * 256 + threadIdx.x;
    if (g >= NODES) return;
    const float* d0 = g_pd + (size_t)g*2*KNN;
    const int*   i0 = g_pi + (size_t)g*2*KNN;
    const float* d1 = d0 + KNN;
    const int*   i1 = i0 + KNN;
    int p = 0, q = 0;
#pragma unroll
    for (int j = 0; j < KNN; ++j) {
        float da = d0[p], db = d1[q];
        bool takeA = (da < db) || (da == db && i0[p] < i1[q]);
        g_nn[(size_t)g*KNN + j] = takeA ? i0[p++] : i1[q++];
    }
}

// ---------------- folded K-predictor MLP + argmax ----------------
__global__ __launch_bounds__(128) void kmlp_kernel() {
    __shared__ float sW1[CH*64];
    __shared__ float sW2[64*KNN];
    __shared__ float sb1[64];
    __shared__ float sb2[KNN];
    for (int t = threadIdx.x; t < CH*64; t += 128) sW1[t] = g_W1c[t];
    for (int t = threadIdx.x; t < 64*KNN; t += 128) sW2[t] = g_W2c[t];
    if (threadIdx.x < 64) sb1[threadIdx.x] = g_b1c[threadIdx.x];
    if (threadIdx.x < KNN) sb2[threadIdx.x] = g_b2c[threadIdx.x];
    __syncthreads();

    int i = blockIdx.x * 128 + threadIdx.x;
    float xr[CH];
#pragma unroll
    for (int c4 = 0; c4 < CH/4; ++c4) {
        float4 v = *(const float4*)(g_xf + (size_t)i*CH + c4*4);
        xr[c4*4+0]=v.x; xr[c4*4+1]=v.y; xr[c4*4+2]=v.z; xr[c4*4+3]=v.w;
    }
    float lg[KNN];
#pragma unroll
    for (int j = 0; j < KNN; ++j) lg[j] = sb2[j];

    for (int h = 0; h < 64; ++h) {
        float a0=0,a1=0,a2=0,a3=0;
#pragma unroll
        for (int c = 0; c < CH; c += 4) {
            a0 = fmaf(xr[c+0], sW1[(c+0)*64+h], a0);
            a1 = fmaf(xr[c+1], sW1[(c+1)*64+h], a1);
            a2 = fmaf(xr[c+2], sW1[(c+2)*64+h], a2);
            a3 = fmaf(xr[c+3], sW1[(c+3)*64+h], a3);
        }
        float hv = fmaxf((a0+a1)+(a2+a3) + sb1[h], 0.f);
#pragma unroll
        for (int j = 0; j < KNN; ++j) lg[j] = fmaf(hv, sW2[h*KNN+j], lg[j]);
    }
    float best = lg[0]; int bi = 0;
#pragma unroll
    for (int j = 1; j < KNN; ++j) if (lg[j] > best) { best = lg[j]; bi = j; }
    g_ki[i] = bi;
}

// ---------------- gather: A = [ki*feat_i | sum_{k<ki} feat_{nn[k]}] ----------------
__global__ void gather_kernel(int mode) {
    const float* feat = mode ? g_h1 : g_xf;
    float*       A    = mode ? g_A2 : g_A1;
    int idx = blockIdx.x * blockDim.x + threadIdx.x;
    if (idx >= NODES*CH) return;
    int i = idx / CH, c = idx % CH;
    int k = g_ki[i];
    const int* nrow = g_nn + (size_t)i*KNN;
    float s = 0.f;
    for (int e = 0; e < k; ++e) s += feat[(size_t)nrow[e]*CH + c];
    A[(size_t)i*192 + c]      = (float)k * feat[(size_t)i*CH + c];
    A[(size_t)i*192 + 96 + c] = s;
}

// ---------------- copy xf into A1[:,0:96] for the final concat ----------------
__global__ void copyxf_kernel() {
    int idx = blockIdx.x * blockDim.x + threadIdx.x;
    if (idx >= NODES*(CH/4)) return;
    int i = idx / (CH/4), c4 = idx % (CH/4);
    ((float4*)(g_A1 + (size_t)i*192))[c4] = ((const float4*)g_xf)[idx];
}

// ---------------- GEMM [25088,192] @ [192, 96-col tile], f32x2-packed ----------------
// mode 0: h1 = relu(A1@Wcat1 + ki*bias)            C=g_h1, ldc=96
// mode 1: h2 = A2@Wcat2 + ki*bias -> A1[:,96:192]  ldc=192
// mode 2: out = relu(A1@Wcat3 + bias3), transposed store into [B,192,N]
__global__ __launch_bounds__(256) void gemm_kernel(int mode, const float* __restrict__ bias_in,
                                                   float* __restrict__ dout) {
    const float* A; const float* W; const float* bias; float* C;
    int ldw, ldc, relu, usek, trans;
    if (mode == 0)      { A=g_A1; W=g_Wcat1; bias=bias_in; C=g_h1;    ldw=96;  ldc=96;  relu=1; usek=1; trans=0; }
    else if (mode == 1) { A=g_A2; W=g_Wcat2; bias=bias_in; C=g_A1+96; ldw=96;  ldc=192; relu=0; usek=1; trans=0; }
    else                { A=g_A1; W=g_Wcat3; bias=g_bias3; C=dout;    ldw=192; ldc=192; relu=1; usek=0; trans=1; }

    __shared__ float As[16][128];
    __shared__ float Bs[16][96];
    int tid = threadIdx.x;
    int tx = tid % 16, ty = tid / 16;
    int row0 = blockIdx.x * 128;
    int col0 = blockIdx.y * 96;

    u64 acc2[4][6];   // packed along row pairs: acc2[p][j] = rows (2p, 2p+1)
#pragma unroll
    for (int p = 0; p < 4; ++p)
#pragma unroll
        for (int j = 0; j < 6; ++j) acc2[p][j] = 0ull;

    for (int kk = 0; kk < 192; kk += 16) {
#pragma unroll
        for (int l = 0; l < 2; ++l) {
            int idx = tid + l*256;
            int r = idx >> 2, k4 = idx & 3;
            float4 v = *(const float4*)(A + (size_t)(row0 + r)*192 + kk + k4*4);
            As[k4*4+0][r] = v.x; As[k4*4+1][r] = v.y; As[k4*4+2][r] = v.z; As[k4*4+3][r] = v.w;
        }
#pragma unroll
        for (int l = 0; l < 2; ++l) {
            int idx = tid + l*256;
            if (idx < 384) {
                int k = idx / 24, c4 = idx % 24;
                float4 v = *(const float4*)(W + (size_t)(kk+k)*ldw + col0 + c4*4);
                *(float4*)&Bs[k][c4*4] = v;
            }
        }
        __syncthreads();
#pragma unroll
        for (int k = 0; k < 16; ++k) {
            // row pairs, naturally packed from shared (16B-aligned)
            ulonglong2 a01 = *(const ulonglong2*)&As[k][ty*8];
            ulonglong2 a23 = *(const ulonglong2*)&As[k][ty*8+4];
            u64 ap[4] = {a01.x, a01.y, a23.x, a23.y};
            float2 bv0 = *(const float2*)&Bs[k][tx*6];
            float2 bv1 = *(const float2*)&Bs[k][tx*6+2];
            float2 bv2 = *(const float2*)&Bs[k][tx*6+4];
            u64 bp[6];
            bp[0] = pack2(bv0.x, bv0.x); bp[1] = pack2(bv0.y, bv0.y);
            bp[2] = pack2(bv1.x, bv1.x); bp[3] = pack2(bv1.y, bv1.y);
            bp[4] = pack2(bv2.x, bv2.x); bp[5] = pack2(bv2.y, bv2.y);
#pragma unroll
            for (int p = 0; p < 4; ++p)
#pragma unroll
                for (int j = 0; j < 6; ++j) ffma2(acc2[p][j], ap[p], bp[j]);
        }
        __syncthreads();
    }

#pragma unroll
    for (int p = 0; p < 4; ++p) {
        int rlo = row0 + ty*8 + 2*p;
        float klo = usek ? (float)g_ki[rlo]   : 1.f;
        float khi = usek ? (float)g_ki[rlo+1] : 1.f;
#pragma unroll
        for (int j = 0; j < 6; ++j) {
            int col = col0 + tx*6 + j;
            float2 v2 = unpack2(acc2[p][j]);
            float vlo = v2.x + bias[col] * klo;
            float vhi = v2.y + bias[col] * khi;
            if (relu) { vlo = fmaxf(vlo, 0.f); vhi = fmaxf(vhi, 0.f); }
            if (trans) {
                int blo = rlo / NPIX, nlo = rlo % NPIX;
                int bhi = (rlo+1) / NPIX, nhi = (rlo+1) % NPIX;
                C[((size_t)(blo*192 + col))*NPIX + nlo] = vlo;
                C[((size_t)(bhi*192 + col))*NPIX + nhi] = vhi;
            } else {
                C[(size_t)rlo*ldc + col]     = vlo;
                C[(size_t)(rlo+1)*ldc + col] = vhi;
            }
        }
    }
}

// ---------------- launch ----------------
extern "C" void kernel_launch(void* const* d_in, const int* in_sizes, int n_in,
                              void* d_out, int out_size) {
    const float* x      = (const float*)d_in[0];
    const float* kmap_w = (const float*)d_in[1];
    const float* kmap_b = (const float*)d_in[2];
    const float* kfc_w  = (const float*)d_in[3];
    const float* kfc_b  = (const float*)d_in[4];
    const float* kmu_w  = (const float*)d_in[5];
    const float* kmu_b  = (const float*)d_in[6];
    const float* kdec_w = (const float*)d_in[7];
    const float* kdec_b = (const float*)d_in[8];
    const float* ec1_w  = (const float*)d_in[9];
    const float* ec1_b  = (const float*)d_in[10];
    const float* ec2_w  = (const float*)d_in[11];
    const float* ec2_b  = (const float*)d_in[12];
    const float* fc_w   = (const float*)d_in[13];
    const float* fc_b   = (const float*)d_in[14];
    const float* io_w   = (const float*)d_in[15];
    const float* io_b   = (const float*)d_in[16];
    const float* up_w   = (const float*)d_in[17];
    const float* up_b   = (const float*)d_in[18];
    float* out = (float*)d_out;

    transpose_kernel<<<dim3(NPIX/32, CH/32, BATCH), dim3(32,32)>>>(x);
    sq_kernel<<<(NODES+255)/256, 256>>>();
    mega_prep<<<315, 256>>>(kmap_w, kmap_b, kfc_w, kfc_b, kmu_w, kmu_b,
                            kdec_w, kdec_b, ec1_w, ec2_w,
                            io_w, io_b, fc_w, fc_b, up_w, up_b);

    dist_topk_kernel<<<dim3(NPIX/64, 2, BATCH), 64>>>();
    merge_topk<<<(NODES+255)/256, 256>>>();
    kmlp_kernel<<<NODES/128, 128>>>();

    gather_kernel<<<(NODES*CH+255)/256, 256>>>(0);
    gemm_kernel<<<dim3(NODES/128, 1), 256>>>(0, ec1_b, nullptr);
    gather_kernel<<<(NODES*CH+255)/256, 256>>>(1);
    copyxf_kernel<<<(NODES*(CH/4)+255)/256, 256>>>();
    gemm_kernel<<<dim3(NODES/128, 1), 256>>>(1, ec2_b, nullptr);
    gemm_kernel<<<dim3(NODES/128, 2), 256>>>(2, nullptr, out);
    (void)in_sizes; (void)n_in; (void)out_size;
}